// round 7
// baseline (speedup 1.0000x reference)
#include <cuda_runtime.h>
#include <cuda_bf16.h>
#include <cstddef>

// Problem constants
#define B_   256
#define T_   200
#define KDEP 5
#define EMB_ 300
#define SMALLD 30
#define IN_DIM 360      // 300 + 30 + 30
#define IN0 390         // 360 + 30
#define MEM_ 300
#define BT_  (B_*T_)    // 51200
#define SSTRIDE 392     // padded row stride for S1 (multiple of 4)

// -------------------- device scratch (static, no allocations) --------------------
__device__ __align__(16) float g_x[(size_t)BT_*IN_DIM + 64];   // x embeddings [BT,360]; reused as S2 [BT,300]
__device__ __align__(16) float g_S[(size_t)BT_*SSTRIDE + 64];  // S1 [BT,392] (cols 0..389 used; 390/391 stay 0)
__device__ __align__(16) float g_h[(size_t)BT_*MEM_ + 64];     // layer-0 output [BT,300]
__device__ float g_invden[BT_];
__device__ float g_maskpad[BT_];                               // fallback mask sink

// -------------------- prep: embedding gathers + dep ragged sum --------------------
__global__ void prep_kernel(const int* __restrict__ words, const int* __restrict__ pos,
                            const int* __restrict__ ner, const int* __restrict__ dep_ids,
                            const int* __restrict__ dep_mask,
                            const float* __restrict__ word_emb, const float* __restrict__ pos_emb,
                            const float* __restrict__ ner_emb, const float* __restrict__ dep_emb)
{
    int warp = threadIdx.x >> 5, lane = threadIdx.x & 31;
    int i = blockIdx.x * 8 + warp;            // token index
    if (i >= BT_) return;

    const float* wrow = word_emb + (size_t)words[i] * EMB_;
    float* xrow = g_x + (size_t)i * IN_DIM;
    #pragma unroll
    for (int j = lane; j < EMB_; j += 32) xrow[j] = wrow[j];

    if (lane < SMALLD) {
        xrow[300 + lane] = pos_emb[pos[i] * SMALLD + lane];
        xrow[330 + lane] = ner_emb[ner[i] * SMALLD + lane];
        float s = 0.f; int cnt = 0;
        #pragma unroll
        for (int k = 0; k < KDEP; k++) {
            int m = dep_mask[i * KDEP + k];
            cnt += m;
            if (m) s += dep_emb[dep_ids[i * KDEP + k] * SMALLD + lane];
        }
        if (cnt == 0) s = dep_emb[lane];          // dep_emb[0]
        s += dep_emb[SMALLD + lane];              // + dep_emb[SELF_LOOP_ID=1]
        g_S[(size_t)i * SSTRIDE + IN_DIM + lane] = s;
    }
}

// -------------------- denom (1/(rowsum+1)) + out_mask --------------------
__global__ void maskden_kernel(const int* __restrict__ adj, float* __restrict__ mask_out)
{
    __shared__ float rs_sh[T_];
    int b = blockIdx.x;
    int tid = threadIdx.x;                     // 256
    const int* Ab = adj + (size_t)b * T_ * T_;

    // colsum (axis 1): coalesced across threads
    int col = 0;
    if (tid < T_) {
        for (int s = 0; s < T_; s++) col += Ab[s * T_ + tid];
    }
    // rowsum (axis 2): warp per row
    int warp = tid >> 5, lane = tid & 31;
    for (int row = warp; row < T_; row += 8) {
        int acc = 0;
        for (int j = lane; j < T_; j += 32) acc += Ab[row * T_ + j];
        #pragma unroll
        for (int off = 16; off; off >>= 1) acc += __shfl_down_sync(0xffffffffu, acc, off);
        if (lane == 0) rs_sh[row] = (float)acc;
    }
    __syncthreads();
    if (tid < T_) {
        float rs = rs_sh[tid];
        g_invden[b * T_ + tid] = 1.0f / (rs + 1.0f);
        mask_out[b * T_ + tid] = ((rs + (float)col) == 0.0f) ? 1.0f : 0.0f;
    }
}

// -------------------- batched einsum: Out[b] = adj[b] @ X[b] + X[b] --------------------
// 64x64 tile, BK=16, 256 threads, 4x4 per thread
__global__ void einsum_kernel(const int* __restrict__ adj,
                              const float* __restrict__ X, int ldx,
                              float* __restrict__ Out, int ldo, int Ncols)
{
    __shared__ __align__(16) float As[16][68];   // transposed A tile, padded
    __shared__ __align__(16) float Bs[16][64];
    const int b  = blockIdx.z;
    const int m0 = blockIdx.y * 64;
    const int n0 = blockIdx.x * 64;
    const int tid = threadIdx.x;
    const int tr = tid >> 4, tc = tid & 15;
    const int* Ab = adj + (size_t)b * (T_ * T_);
    const float* Xb = X + (size_t)b * T_ * ldx;

    float acc[4][4] = {};
    for (int k0 = 0; k0 < T_; k0 += 16) {
        #pragma unroll
        for (int i = 0; i < 4; i++) {
            int idx = tid + i * 256;           // 0..1023, 64x16 tile
            int r = idx >> 4, c = idx & 15;
            int gm = m0 + r, gk = k0 + c;
            As[c][r] = (gm < T_ && gk < T_) ? (float)Ab[gm * T_ + gk] : 0.f;
        }
        #pragma unroll
        for (int i = 0; i < 4; i++) {
            int idx = tid + i * 256;           // 16x64 tile
            int r = idx >> 6, c = idx & 63;
            int gk = k0 + r, gn = n0 + c;
            Bs[r][c] = (gk < T_ && gn < Ncols) ? Xb[gk * ldx + gn] : 0.f;
        }
        __syncthreads();
        #pragma unroll
        for (int kk = 0; kk < 16; kk++) {
            float4 a  = *reinterpret_cast<const float4*>(&As[kk][tr * 4]);
            float4 bv = *reinterpret_cast<const float4*>(&Bs[kk][tc * 4]);
            float av[4] = {a.x, a.y, a.z, a.w};
            float bw[4] = {bv.x, bv.y, bv.z, bv.w};
            #pragma unroll
            for (int i = 0; i < 4; i++)
                #pragma unroll
                for (int j = 0; j < 4; j++)
                    acc[i][j] = fmaf(av[i], bw[j], acc[i][j]);
        }
        __syncthreads();
    }
    #pragma unroll
    for (int i = 0; i < 4; i++) {
        int m = m0 + tr * 4 + i;
        if (m >= T_) continue;
        #pragma unroll
        for (int j = 0; j < 4; j++) {
            int n = n0 + tc * 4 + j;
            if (n >= Ncols) continue;
            Out[((size_t)b * T_ + m) * ldo + n] = acc[i][j] + Xb[m * ldx + n];
        }
    }
}

// -------------------- dense GEMM: C = relu((A@W + 2*bias) * invden) --------------------
// 128x64 tile, BK=16, 256 threads, 8x4 per thread. Requires M % 128 == 0, lda % 4 == 0.
// A tile loaded unguarded as float4 (caller guarantees padded/owned memory past row end);
// out-of-range K columns multiply against guarded zeros in Bs.
__global__ void dense_gemm_kernel(const float* __restrict__ A, int lda,
                                  const float* __restrict__ W, int K, int N,
                                  const float* __restrict__ bias,
                                  const float* __restrict__ invden,
                                  float* __restrict__ C, int ldc)
{
    __shared__ __align__(16) float As[16][132];  // transposed, padded
    __shared__ __align__(16) float Bs[16][64];
    const int tid = threadIdx.x;
    const int m0 = blockIdx.y * 128;
    const int n0 = blockIdx.x * 64;
    const int tr = tid >> 4, tc = tid & 15;

    float acc[8][4] = {};
    for (int k0 = 0; k0 < K; k0 += 16) {
        #pragma unroll
        for (int i = 0; i < 2; i++) {
            int idx = tid + i * 256;            // 0..511 float4 slots (128x16)
            int r = idx >> 2, cq = idx & 3;
            float4 av = *reinterpret_cast<const float4*>(
                &A[(size_t)(m0 + r) * lda + k0 + cq * 4]);
            As[cq * 4 + 0][r] = av.x;
            As[cq * 4 + 1][r] = av.y;
            As[cq * 4 + 2][r] = av.z;
            As[cq * 4 + 3][r] = av.w;
        }
        #pragma unroll
        for (int i = 0; i < 4; i++) {
            int idx = tid + i * 256;            // 16x64 tile
            int r = idx >> 6, c = idx & 63;
            int gk = k0 + r, gn = n0 + c;
            Bs[r][c] = (gk < K && gn < N) ? W[(size_t)gk * N + gn] : 0.f;
        }
        __syncthreads();
        #pragma unroll
        for (int kk = 0; kk < 16; kk++) {
            float4 a0 = *reinterpret_cast<const float4*>(&As[kk][tr * 8]);
            float4 a1 = *reinterpret_cast<const float4*>(&As[kk][tr * 8 + 4]);
            float4 bv = *reinterpret_cast<const float4*>(&Bs[kk][tc * 4]);
            float av[8] = {a0.x, a0.y, a0.z, a0.w, a1.x, a1.y, a1.z, a1.w};
            float bw[4] = {bv.x, bv.y, bv.z, bv.w};
            #pragma unroll
            for (int i = 0; i < 8; i++)
                #pragma unroll
                for (int j = 0; j < 4; j++)
                    acc[i][j] = fmaf(av[i], bw[j], acc[i][j]);
        }
        __syncthreads();
    }
    #pragma unroll
    for (int i = 0; i < 8; i++) {
        int m = m0 + tr * 8 + i;
        float inv = invden[m];
        #pragma unroll
        for (int j = 0; j < 4; j++) {
            int n = n0 + tc * 4 + j;
            if (n >= N) continue;
            float v = (acc[i][j] + 2.0f * bias[n]) * inv;
            C[(size_t)m * ldc + n] = fmaxf(v, 0.0f);
        }
    }
}

// -------------------- launch --------------------
extern "C" void kernel_launch(void* const* d_in, const int* in_sizes, int n_in,
                              void* d_out, int out_size)
{
    const int* adj      = (const int*)d_in[0];
    const int* words    = (const int*)d_in[1];
    const int* pos      = (const int*)d_in[2];
    const int* ner      = (const int*)d_in[3];
    const int* dep_ids  = (const int*)d_in[4];
    const int* dep_mask = (const int*)d_in[5];
    // maxlen may or may not be materialized as an input; the 8 trailing arrays
    // (word_emb, pos_emb, ner_emb, dep_emb, W0_w, W0_b, W1_w, W1_b) are fixed.
    int base = n_in - 8;
    const float* word_emb = (const float*)d_in[base + 0];
    const float* pos_emb  = (const float*)d_in[base + 1];
    const float* ner_emb  = (const float*)d_in[base + 2];
    const float* dep_emb  = (const float*)d_in[base + 3];
    const float* W0_w     = (const float*)d_in[base + 4];
    const float* W0_b     = (const float*)d_in[base + 5];
    const float* W1_w     = (const float*)d_in[base + 6];
    const float* W1_b     = (const float*)d_in[base + 7];

    float* out = (float*)d_out;

    // scratch symbol addresses (no allocation; capture-safe host API)
    void *px, *pS, *ph, *pinv, *pmaskpad;
    cudaGetSymbolAddress(&px, g_x);
    cudaGetSymbolAddress(&pS, g_S);
    cudaGetSymbolAddress(&ph, g_h);
    cudaGetSymbolAddress(&pinv, g_invden);
    cudaGetSymbolAddress(&pmaskpad, g_maskpad);
    float* gx   = (float*)px;
    float* gS   = (float*)pS;
    float* gh   = (float*)ph;
    float* ginv = (float*)pinv;

    // mask goes at out + BT*300 if out_size includes it, else to a scratch sink
    float* mask_out = ((long long)out_size >= (long long)BT_ * MEM_ + BT_)
                        ? (out + (size_t)BT_ * MEM_) : (float*)pmaskpad;

    dim3 blk(256);

    // 1) embeddings + dep concat columns of S1
    prep_kernel<<<BT_ / 8, blk>>>(words, pos, ner, dep_ids, dep_mask,
                                  word_emb, pos_emb, ner_emb, dep_emb);

    // 2) denom + out_mask
    maskden_kernel<<<B_, blk>>>(adj, mask_out);

    // 3) S1[:, :360] = A@x + x
    einsum_kernel<<<dim3(6, 4, B_), blk>>>(adj, gx, IN_DIM, gS, SSTRIDE, IN_DIM);

    // 4) h = relu((S1 @ W0 + 2*b0) * invden)
    dense_gemm_kernel<<<dim3(5, BT_ / 128), blk>>>(gS, SSTRIDE, W0_w, IN0, MEM_,
                                                   W0_b, ginv, gh, MEM_);

    // 5) S2 = A@h + h   (reuse g_x as S2, stride 300)
    einsum_kernel<<<dim3(5, 4, B_), blk>>>(adj, gh, MEM_, gx, MEM_, MEM_);

    // 6) out = relu((S2 @ W1 + 2*b1) * invden)
    dense_gemm_kernel<<<dim3(5, BT_ / 128), blk>>>(gx, MEM_, W1_w, MEM_, MEM_,
                                                   W1_b, ginv, out, MEM_);
}

// round 8
// speedup vs baseline: 1.0027x; 1.0027x over previous
#include <cuda_runtime.h>
#include <cuda_bf16.h>
#include <cstddef>

// Problem constants
#define B_   256
#define T_   200
#define KDEP 5
#define EMB_ 300
#define SMALLD 30
#define IN_DIM 360      // 300 + 30 + 30
#define IN0 390         // 360 + 30
#define MEM_ 300
#define BT_  (B_*T_)    // 51200
#define SSTRIDE 392     // padded row stride for S1 (multiple of 4)

// -------------------- device scratch (static, no allocations) --------------------
__device__ __align__(16) float g_x[(size_t)BT_*IN_DIM + 64];   // x embeddings [BT,360]; reused as S2 [BT,300]
__device__ __align__(16) float g_S[(size_t)BT_*SSTRIDE + 64];  // S1 [BT,392] (cols 0..389 used; 390/391 stay 0)
__device__ __align__(16) float g_h[(size_t)BT_*MEM_ + 64];     // layer-0 output [BT,300]
__device__ float g_invden[BT_];
__device__ float g_maskpad[BT_];                               // fallback mask sink

// -------------------- prep: embedding gathers + dep ragged sum --------------------
__global__ void prep_kernel(const int* __restrict__ words, const int* __restrict__ pos,
                            const int* __restrict__ ner, const int* __restrict__ dep_ids,
                            const int* __restrict__ dep_mask,
                            const float* __restrict__ word_emb, const float* __restrict__ pos_emb,
                            const float* __restrict__ ner_emb, const float* __restrict__ dep_emb)
{
    int warp = threadIdx.x >> 5, lane = threadIdx.x & 31;
    int i = blockIdx.x * 8 + warp;            // token index
    if (i >= BT_) return;

    const float* wrow = word_emb + (size_t)words[i] * EMB_;
    float* xrow = g_x + (size_t)i * IN_DIM;
    #pragma unroll
    for (int j = lane; j < EMB_; j += 32) xrow[j] = wrow[j];

    if (lane < SMALLD) {
        xrow[300 + lane] = pos_emb[pos[i] * SMALLD + lane];
        xrow[330 + lane] = ner_emb[ner[i] * SMALLD + lane];
        float s = 0.f; int cnt = 0;
        #pragma unroll
        for (int k = 0; k < KDEP; k++) {
            int m = dep_mask[i * KDEP + k];
            cnt += m;
            if (m) s += dep_emb[dep_ids[i * KDEP + k] * SMALLD + lane];
        }
        if (cnt == 0) s = dep_emb[lane];          // dep_emb[0]
        s += dep_emb[SMALLD + lane];              // + dep_emb[SELF_LOOP_ID=1]
        g_S[(size_t)i * SSTRIDE + IN_DIM + lane] = s;
    }
}

// -------------------- denom (1/(rowsum+1)) + out_mask --------------------
__global__ void maskden_kernel(const int* __restrict__ adj, float* __restrict__ mask_out)
{
    __shared__ float rs_sh[T_];
    int b = blockIdx.x;
    int tid = threadIdx.x;                     // 256
    const int* Ab = adj + (size_t)b * T_ * T_;

    // colsum (axis 1): coalesced across threads
    int col = 0;
    if (tid < T_) {
        for (int s = 0; s < T_; s++) col += Ab[s * T_ + tid];
    }
    // rowsum (axis 2): warp per row
    int warp = tid >> 5, lane = tid & 31;
    for (int row = warp; row < T_; row += 8) {
        int acc = 0;
        for (int j = lane; j < T_; j += 32) acc += Ab[row * T_ + j];
        #pragma unroll
        for (int off = 16; off; off >>= 1) acc += __shfl_down_sync(0xffffffffu, acc, off);
        if (lane == 0) rs_sh[row] = (float)acc;
    }
    __syncthreads();
    if (tid < T_) {
        float rs = rs_sh[tid];
        g_invden[b * T_ + tid] = 1.0f / (rs + 1.0f);
        mask_out[b * T_ + tid] = ((rs + (float)col) == 0.0f) ? 1.0f : 0.0f;
    }
}

// -------------------- batched einsum: Out[b] = adj[b] @ X[b] + X[b] --------------------
// 64x64 tile, BK=16, 256 threads, 4x4 per thread
__global__ void einsum_kernel(const int* __restrict__ adj,
                              const float* __restrict__ X, int ldx,
                              float* __restrict__ Out, int ldo, int Ncols)
{
    __shared__ __align__(16) float As[16][68];   // transposed A tile, padded
    __shared__ __align__(16) float Bs[16][64];
    const int b  = blockIdx.z;
    const int m0 = blockIdx.y * 64;
    const int n0 = blockIdx.x * 64;
    const int tid = threadIdx.x;
    const int tr = tid >> 4, tc = tid & 15;
    const int* Ab = adj + (size_t)b * (T_ * T_);
    const float* Xb = X + (size_t)b * T_ * ldx;

    float acc[4][4] = {};
    for (int k0 = 0; k0 < T_; k0 += 16) {
        #pragma unroll
        for (int i = 0; i < 4; i++) {
            int idx = tid + i * 256;           // 0..1023, 64x16 tile
            int r = idx >> 4, c = idx & 15;
            int gm = m0 + r, gk = k0 + c;
            As[c][r] = (gm < T_ && gk < T_) ? (float)Ab[gm * T_ + gk] : 0.f;
        }
        #pragma unroll
        for (int i = 0; i < 4; i++) {
            int idx = tid + i * 256;           // 16x64 tile
            int r = idx >> 6, c = idx & 63;
            int gk = k0 + r, gn = n0 + c;
            Bs[r][c] = (gk < T_ && gn < Ncols) ? Xb[gk * ldx + gn] : 0.f;
        }
        __syncthreads();
        #pragma unroll
        for (int kk = 0; kk < 16; kk++) {
            float4 a  = *reinterpret_cast<const float4*>(&As[kk][tr * 4]);
            float4 bv = *reinterpret_cast<const float4*>(&Bs[kk][tc * 4]);
            float av[4] = {a.x, a.y, a.z, a.w};
            float bw[4] = {bv.x, bv.y, bv.z, bv.w};
            #pragma unroll
            for (int i = 0; i < 4; i++)
                #pragma unroll
                for (int j = 0; j < 4; j++)
                    acc[i][j] = fmaf(av[i], bw[j], acc[i][j]);
        }
        __syncthreads();
    }
    #pragma unroll
    for (int i = 0; i < 4; i++) {
        int m = m0 + tr * 4 + i;
        if (m >= T_) continue;
        #pragma unroll
        for (int j = 0; j < 4; j++) {
            int n = n0 + tc * 4 + j;
            if (n >= Ncols) continue;
            Out[((size_t)b * T_ + m) * ldo + n] = acc[i][j] + Xb[m * ldx + n];
        }
    }
}

// -------------------- dense GEMM: C = relu((A@W + 2*bias) * invden) --------------------
// 128x64 tile, BK=16, 256 threads, 8x4 per thread. Requires M % 128 == 0, lda % 4 == 0.
// A tile loaded unguarded as float4 (caller guarantees padded/owned memory past row end);
// out-of-range K columns multiply against guarded zeros in Bs.
__global__ void dense_gemm_kernel(const float* __restrict__ A, int lda,
                                  const float* __restrict__ W, int K, int N,
                                  const float* __restrict__ bias,
                                  const float* __restrict__ invden,
                                  float* __restrict__ C, int ldc)
{
    __shared__ __align__(16) float As[16][132];  // transposed, padded
    __shared__ __align__(16) float Bs[16][64];
    const int tid = threadIdx.x;
    const int m0 = blockIdx.y * 128;
    const int n0 = blockIdx.x * 64;
    const int tr = tid >> 4, tc = tid & 15;

    float acc[8][4] = {};
    for (int k0 = 0; k0 < K; k0 += 16) {
        #pragma unroll
        for (int i = 0; i < 2; i++) {
            int idx = tid + i * 256;            // 0..511 float4 slots (128x16)
            int r = idx >> 2, cq = idx & 3;
            float4 av = *reinterpret_cast<const float4*>(
                &A[(size_t)(m0 + r) * lda + k0 + cq * 4]);
            As[cq * 4 + 0][r] = av.x;
            As[cq * 4 + 1][r] = av.y;
            As[cq * 4 + 2][r] = av.z;
            As[cq * 4 + 3][r] = av.w;
        }
        #pragma unroll
        for (int i = 0; i < 4; i++) {
            int idx = tid + i * 256;            // 16x64 tile
            int r = idx >> 6, c = idx & 63;
            int gk = k0 + r, gn = n0 + c;
            Bs[r][c] = (gk < K && gn < N) ? W[(size_t)gk * N + gn] : 0.f;
        }
        __syncthreads();
        #pragma unroll
        for (int kk = 0; kk < 16; kk++) {
            float4 a0 = *reinterpret_cast<const float4*>(&As[kk][tr * 8]);
            float4 a1 = *reinterpret_cast<const float4*>(&As[kk][tr * 8 + 4]);
            float4 bv = *reinterpret_cast<const float4*>(&Bs[kk][tc * 4]);
            float av[8] = {a0.x, a0.y, a0.z, a0.w, a1.x, a1.y, a1.z, a1.w};
            float bw[4] = {bv.x, bv.y, bv.z, bv.w};
            #pragma unroll
            for (int i = 0; i < 8; i++)
                #pragma unroll
                for (int j = 0; j < 4; j++)
                    acc[i][j] = fmaf(av[i], bw[j], acc[i][j]);
        }
        __syncthreads();
    }
    #pragma unroll
    for (int i = 0; i < 8; i++) {
        int m = m0 + tr * 8 + i;
        float inv = invden[m];
        #pragma unroll
        for (int j = 0; j < 4; j++) {
            int n = n0 + tc * 4 + j;
            if (n >= N) continue;
            float v = (acc[i][j] + 2.0f * bias[n]) * inv;
            C[(size_t)m * ldc + n] = fmaxf(v, 0.0f);
        }
    }
}

// -------------------- launch --------------------
extern "C" void kernel_launch(void* const* d_in, const int* in_sizes, int n_in,
                              void* d_out, int out_size)
{
    const int* adj      = (const int*)d_in[0];
    const int* words    = (const int*)d_in[1];
    const int* pos      = (const int*)d_in[2];
    const int* ner      = (const int*)d_in[3];
    const int* dep_ids  = (const int*)d_in[4];
    const int* dep_mask = (const int*)d_in[5];
    // maxlen may or may not be materialized as an input; the 8 trailing arrays
    // (word_emb, pos_emb, ner_emb, dep_emb, W0_w, W0_b, W1_w, W1_b) are fixed.
    int base = n_in - 8;
    const float* word_emb = (const float*)d_in[base + 0];
    const float* pos_emb  = (const float*)d_in[base + 1];
    const float* ner_emb  = (const float*)d_in[base + 2];
    const float* dep_emb  = (const float*)d_in[base + 3];
    const float* W0_w     = (const float*)d_in[base + 4];
    const float* W0_b     = (const float*)d_in[base + 5];
    const float* W1_w     = (const float*)d_in[base + 6];
    const float* W1_b     = (const float*)d_in[base + 7];

    float* out = (float*)d_out;

    // scratch symbol addresses (no allocation; capture-safe host API)
    void *px, *pS, *ph, *pinv, *pmaskpad;
    cudaGetSymbolAddress(&px, g_x);
    cudaGetSymbolAddress(&pS, g_S);
    cudaGetSymbolAddress(&ph, g_h);
    cudaGetSymbolAddress(&pinv, g_invden);
    cudaGetSymbolAddress(&pmaskpad, g_maskpad);
    float* gx   = (float*)px;
    float* gS   = (float*)pS;
    float* gh   = (float*)ph;
    float* ginv = (float*)pinv;

    // mask goes at out + BT*300 if out_size includes it, else to a scratch sink
    float* mask_out = ((long long)out_size >= (long long)BT_ * MEM_ + BT_)
                        ? (out + (size_t)BT_ * MEM_) : (float*)pmaskpad;

    dim3 blk(256);

    // 1) embeddings + dep concat columns of S1
    prep_kernel<<<BT_ / 8, blk>>>(words, pos, ner, dep_ids, dep_mask,
                                  word_emb, pos_emb, ner_emb, dep_emb);

    // 2) denom + out_mask
    maskden_kernel<<<B_, blk>>>(adj, mask_out);

    // 3) S1[:, :360] = A@x + x
    einsum_kernel<<<dim3(6, 4, B_), blk>>>(adj, gx, IN_DIM, gS, SSTRIDE, IN_DIM);

    // 4) h = relu((S1 @ W0 + 2*b0) * invden)
    dense_gemm_kernel<<<dim3(5, BT_ / 128), blk>>>(gS, SSTRIDE, W0_w, IN0, MEM_,
                                                   W0_b, ginv, gh, MEM_);

    // 5) S2 = A@h + h   (reuse g_x as S2, stride 300)
    einsum_kernel<<<dim3(5, 4, B_), blk>>>(adj, gh, MEM_, gx, MEM_, MEM_);

    // 6) out = relu((S2 @ W1 + 2*b1) * invden)
    dense_gemm_kernel<<<dim3(5, BT_ / 128), blk>>>(gx, MEM_, W1_w, MEM_, MEM_,
                                                   W1_b, ginv, out, MEM_);
}

// round 9
// speedup vs baseline: 1.0045x; 1.0017x over previous
#include <cuda_runtime.h>
#include <cuda_bf16.h>
#include <cstddef>

// Problem constants
#define B_   256
#define T_   200
#define KDEP 5
#define EMB_ 300
#define SMALLD 30
#define IN_DIM 360      // 300 + 30 + 30
#define IN0 390         // 360 + 30
#define MEM_ 300
#define BT_  (B_*T_)    // 51200
#define SSTRIDE 392     // padded row stride for S1 (multiple of 4)

// -------------------- device scratch (static, no allocations) --------------------
__device__ __align__(16) float g_x[(size_t)BT_*IN_DIM + 64];   // x embeddings [BT,360]; reused as S2 [BT,300]
__device__ __align__(16) float g_S[(size_t)BT_*SSTRIDE + 64];  // S1 [BT,392] (cols 0..389 used; 390/391 stay 0)
__device__ __align__(16) float g_h[(size_t)BT_*MEM_ + 64];     // layer-0 output [BT,300]
__device__ float g_invden[BT_];
__device__ float g_maskpad[BT_];                               // fallback mask sink

// -------------------- prep: embedding gathers + dep ragged sum --------------------
__global__ void prep_kernel(const int* __restrict__ words, const int* __restrict__ pos,
                            const int* __restrict__ ner, const int* __restrict__ dep_ids,
                            const int* __restrict__ dep_mask,
                            const float* __restrict__ word_emb, const float* __restrict__ pos_emb,
                            const float* __restrict__ ner_emb, const float* __restrict__ dep_emb)
{
    int warp = threadIdx.x >> 5, lane = threadIdx.x & 31;
    int i = blockIdx.x * 8 + warp;            // token index
    if (i >= BT_) return;

    const float* wrow = word_emb + (size_t)words[i] * EMB_;
    float* xrow = g_x + (size_t)i * IN_DIM;
    #pragma unroll
    for (int j = lane; j < EMB_; j += 32) xrow[j] = wrow[j];

    if (lane < SMALLD) {
        xrow[300 + lane] = pos_emb[pos[i] * SMALLD + lane];
        xrow[330 + lane] = ner_emb[ner[i] * SMALLD + lane];
        float s = 0.f; int cnt = 0;
        #pragma unroll
        for (int k = 0; k < KDEP; k++) {
            int m = dep_mask[i * KDEP + k];
            cnt += m;
            if (m) s += dep_emb[dep_ids[i * KDEP + k] * SMALLD + lane];
        }
        if (cnt == 0) s = dep_emb[lane];          // dep_emb[0]
        s += dep_emb[SMALLD + lane];              // + dep_emb[SELF_LOOP_ID=1]
        g_S[(size_t)i * SSTRIDE + IN_DIM + lane] = s;
    }
}

// -------------------- denom (1/(rowsum+1)) + out_mask --------------------
__global__ void maskden_kernel(const int* __restrict__ adj, float* __restrict__ mask_out)
{
    __shared__ float rs_sh[T_];
    int b = blockIdx.x;
    int tid = threadIdx.x;                     // 256
    const int* Ab = adj + (size_t)b * T_ * T_;

    // colsum (axis 1): coalesced across threads
    int col = 0;
    if (tid < T_) {
        for (int s = 0; s < T_; s++) col += Ab[s * T_ + tid];
    }
    // rowsum (axis 2): warp per row
    int warp = tid >> 5, lane = tid & 31;
    for (int row = warp; row < T_; row += 8) {
        int acc = 0;
        for (int j = lane; j < T_; j += 32) acc += Ab[row * T_ + j];
        #pragma unroll
        for (int off = 16; off; off >>= 1) acc += __shfl_down_sync(0xffffffffu, acc, off);
        if (lane == 0) rs_sh[row] = (float)acc;
    }
    __syncthreads();
    if (tid < T_) {
        float rs = rs_sh[tid];
        g_invden[b * T_ + tid] = 1.0f / (rs + 1.0f);
        mask_out[b * T_ + tid] = ((rs + (float)col) == 0.0f) ? 1.0f : 0.0f;
    }
}

// -------------------- batched einsum: Out[b] = adj[b] @ X[b] + X[b] --------------------
// 64x64 tile, BK=16, 256 threads, 4x4 per thread
__global__ void einsum_kernel(const int* __restrict__ adj,
                              const float* __restrict__ X, int ldx,
                              float* __restrict__ Out, int ldo, int Ncols)
{
    __shared__ __align__(16) float As[16][68];   // transposed A tile, padded
    __shared__ __align__(16) float Bs[16][64];
    const int b  = blockIdx.z;
    const int m0 = blockIdx.y * 64;
    const int n0 = blockIdx.x * 64;
    const int tid = threadIdx.x;
    const int tr = tid >> 4, tc = tid & 15;
    const int* Ab = adj + (size_t)b * (T_ * T_);
    const float* Xb = X + (size_t)b * T_ * ldx;

    float acc[4][4] = {};
    for (int k0 = 0; k0 < T_; k0 += 16) {
        #pragma unroll
        for (int i = 0; i < 4; i++) {
            int idx = tid + i * 256;           // 0..1023, 64x16 tile
            int r = idx >> 4, c = idx & 15;
            int gm = m0 + r, gk = k0 + c;
            As[c][r] = (gm < T_ && gk < T_) ? (float)Ab[gm * T_ + gk] : 0.f;
        }
        #pragma unroll
        for (int i = 0; i < 4; i++) {
            int idx = tid + i * 256;           // 16x64 tile
            int r = idx >> 6, c = idx & 63;
            int gk = k0 + r, gn = n0 + c;
            Bs[r][c] = (gk < T_ && gn < Ncols) ? Xb[gk * ldx + gn] : 0.f;
        }
        __syncthreads();
        #pragma unroll
        for (int kk = 0; kk < 16; kk++) {
            float4 a  = *reinterpret_cast<const float4*>(&As[kk][tr * 4]);
            float4 bv = *reinterpret_cast<const float4*>(&Bs[kk][tc * 4]);
            float av[4] = {a.x, a.y, a.z, a.w};
            float bw[4] = {bv.x, bv.y, bv.z, bv.w};
            #pragma unroll
            for (int i = 0; i < 4; i++)
                #pragma unroll
                for (int j = 0; j < 4; j++)
                    acc[i][j] = fmaf(av[i], bw[j], acc[i][j]);
        }
        __syncthreads();
    }
    #pragma unroll
    for (int i = 0; i < 4; i++) {
        int m = m0 + tr * 4 + i;
        if (m >= T_) continue;
        #pragma unroll
        for (int j = 0; j < 4; j++) {
            int n = n0 + tc * 4 + j;
            if (n >= Ncols) continue;
            Out[((size_t)b * T_ + m) * ldo + n] = acc[i][j] + Xb[m * ldx + n];
        }
    }
}

// -------------------- dense GEMM: C = relu((A@W + 2*bias) * invden) --------------------
// 128x64 tile, BK=16, 256 threads, 8x4 per thread. Requires M % 128 == 0, lda % 4 == 0.
// A tile loaded unguarded as float4 (caller guarantees padded/owned memory past row end);
// out-of-range K columns multiply against guarded zeros in Bs.
__global__ void dense_gemm_kernel(const float* __restrict__ A, int lda,
                                  const float* __restrict__ W, int K, int N,
                                  const float* __restrict__ bias,
                                  const float* __restrict__ invden,
                                  float* __restrict__ C, int ldc)
{
    __shared__ __align__(16) float As[16][132];  // transposed, padded
    __shared__ __align__(16) float Bs[16][64];
    const int tid = threadIdx.x;
    const int m0 = blockIdx.y * 128;
    const int n0 = blockIdx.x * 64;
    const int tr = tid >> 4, tc = tid & 15;

    float acc[8][4] = {};
    for (int k0 = 0; k0 < K; k0 += 16) {
        #pragma unroll
        for (int i = 0; i < 2; i++) {
            int idx = tid + i * 256;            // 0..511 float4 slots (128x16)
            int r = idx >> 2, cq = idx & 3;
            float4 av = *reinterpret_cast<const float4*>(
                &A[(size_t)(m0 + r) * lda + k0 + cq * 4]);
            As[cq * 4 + 0][r] = av.x;
            As[cq * 4 + 1][r] = av.y;
            As[cq * 4 + 2][r] = av.z;
            As[cq * 4 + 3][r] = av.w;
        }
        #pragma unroll
        for (int i = 0; i < 4; i++) {
            int idx = tid + i * 256;            // 16x64 tile
            int r = idx >> 6, c = idx & 63;
            int gk = k0 + r, gn = n0 + c;
            Bs[r][c] = (gk < K && gn < N) ? W[(size_t)gk * N + gn] : 0.f;
        }
        __syncthreads();
        #pragma unroll
        for (int kk = 0; kk < 16; kk++) {
            float4 a0 = *reinterpret_cast<const float4*>(&As[kk][tr * 8]);
            float4 a1 = *reinterpret_cast<const float4*>(&As[kk][tr * 8 + 4]);
            float4 bv = *reinterpret_cast<const float4*>(&Bs[kk][tc * 4]);
            float av[8] = {a0.x, a0.y, a0.z, a0.w, a1.x, a1.y, a1.z, a1.w};
            float bw[4] = {bv.x, bv.y, bv.z, bv.w};
            #pragma unroll
            for (int i = 0; i < 8; i++)
                #pragma unroll
                for (int j = 0; j < 4; j++)
                    acc[i][j] = fmaf(av[i], bw[j], acc[i][j]);
        }
        __syncthreads();
    }
    #pragma unroll
    for (int i = 0; i < 8; i++) {
        int m = m0 + tr * 8 + i;
        float inv = invden[m];
        #pragma unroll
        for (int j = 0; j < 4; j++) {
            int n = n0 + tc * 4 + j;
            if (n >= N) continue;
            float v = (acc[i][j] + 2.0f * bias[n]) * inv;
            C[(size_t)m * ldc + n] = fmaxf(v, 0.0f);
        }
    }
}

// -------------------- launch --------------------
extern "C" void kernel_launch(void* const* d_in, const int* in_sizes, int n_in,
                              void* d_out, int out_size)
{
    const int* adj      = (const int*)d_in[0];
    const int* words    = (const int*)d_in[1];
    const int* pos      = (const int*)d_in[2];
    const int* ner      = (const int*)d_in[3];
    const int* dep_ids  = (const int*)d_in[4];
    const int* dep_mask = (const int*)d_in[5];
    // maxlen may or may not be materialized as an input; the 8 trailing arrays
    // (word_emb, pos_emb, ner_emb, dep_emb, W0_w, W0_b, W1_w, W1_b) are fixed.
    int base = n_in - 8;
    const float* word_emb = (const float*)d_in[base + 0];
    const float* pos_emb  = (const float*)d_in[base + 1];
    const float* ner_emb  = (const float*)d_in[base + 2];
    const float* dep_emb  = (const float*)d_in[base + 3];
    const float* W0_w     = (const float*)d_in[base + 4];
    const float* W0_b     = (const float*)d_in[base + 5];
    const float* W1_w     = (const float*)d_in[base + 6];
    const float* W1_b     = (const float*)d_in[base + 7];

    float* out = (float*)d_out;

    // scratch symbol addresses (no allocation; capture-safe host API)
    void *px, *pS, *ph, *pinv, *pmaskpad;
    cudaGetSymbolAddress(&px, g_x);
    cudaGetSymbolAddress(&pS, g_S);
    cudaGetSymbolAddress(&ph, g_h);
    cudaGetSymbolAddress(&pinv, g_invden);
    cudaGetSymbolAddress(&pmaskpad, g_maskpad);
    float* gx   = (float*)px;
    float* gS   = (float*)pS;
    float* gh   = (float*)ph;
    float* ginv = (float*)pinv;

    // mask goes at out + BT*300 if out_size includes it, else to a scratch sink
    float* mask_out = ((long long)out_size >= (long long)BT_ * MEM_ + BT_)
                        ? (out + (size_t)BT_ * MEM_) : (float*)pmaskpad;

    dim3 blk(256);

    // 1) embeddings + dep concat columns of S1
    prep_kernel<<<BT_ / 8, blk>>>(words, pos, ner, dep_ids, dep_mask,
                                  word_emb, pos_emb, ner_emb, dep_emb);

    // 2) denom + out_mask
    maskden_kernel<<<B_, blk>>>(adj, mask_out);

    // 3) S1[:, :360] = A@x + x
    einsum_kernel<<<dim3(6, 4, B_), blk>>>(adj, gx, IN_DIM, gS, SSTRIDE, IN_DIM);

    // 4) h = relu((S1 @ W0 + 2*b0) * invden)
    dense_gemm_kernel<<<dim3(5, BT_ / 128), blk>>>(gS, SSTRIDE, W0_w, IN0, MEM_,
                                                   W0_b, ginv, gh, MEM_);

    // 5) S2 = A@h + h   (reuse g_x as S2, stride 300)
    einsum_kernel<<<dim3(5, 4, B_), blk>>>(adj, gh, MEM_, gx, MEM_, MEM_);

    // 6) out = relu((S2 @ W1 + 2*b1) * invden)
    dense_gemm_kernel<<<dim3(5, BT_ / 128), blk>>>(gx, MEM_, W1_w, MEM_, MEM_,
                                                   W1_b, ginv, out, MEM_);
}